// round 2
// baseline (speedup 1.0000x reference)
#include <cuda_runtime.h>
#include <cstdint>

#define NV 778
#define NF 1538
#define NB 4
#define OW 128
#define OH 128
#define BGD 1e10f
#define NSLICE 4
#define CHUNK ((NF + NSLICE - 1) / NSLICE)   // 385

// Scratch (no allocation allowed): precomputed face data + uint z-buffer.
// Face record: 5 float4 per (batch, face):
//   [0] bbox  (xmin, xmax, ymin, ymax)
//   [1] edge0 (s*dx, s*dy, refx, refy)   e0' = s*dx*(py-refy) - s*dy*(px-refx)
//   [2] edge1
//   [3] edge2
//   [4] w     (z0/|area|, z1/|area|, z2/|area|, 0)
__device__ float4 g_face[NB * NF * 5];
__device__ unsigned int g_zbuf[NB * OH * OW];

__global__ void __launch_bounds__(256) setup_kernel(
    const float* __restrict__ verts, const int* __restrict__ faces)
{
    int idx = blockIdx.x * blockDim.x + threadIdx.x;

    // z-buffer init (positive floats: uint bit pattern is order-preserving)
    if (idx < NB * OH * OW) g_zbuf[idx] = __float_as_uint(BGD);

    if (idx >= NB * NF) return;
    int b = idx / NF;
    int f = idx - b * NF;

    // faces are int32 on device (JAX x64 disabled: astype(int64) -> int32).
    // Clamp defensively so a dtype surprise can't fault.
    int i0 = min(max(faces[f * 3 + 0], 0), NV - 1);
    int i1 = min(max(faces[f * 3 + 1], 0), NV - 1);
    int i2 = min(max(faces[f * 3 + 2], 0), NV - 1);
    const float* vb = verts + (size_t)b * NV * 3;
    float x0 = vb[i0 * 3 + 0], y0 = vb[i0 * 3 + 1], z0 = vb[i0 * 3 + 2];
    float x1 = vb[i1 * 3 + 0], y1 = vb[i1 * 3 + 1], z1 = vb[i1 * 3 + 2];
    float x2 = vb[i2 * 3 + 0], y2 = vb[i2 * 3 + 1], z2 = vb[i2 * 3 + 2];

    // area = (x1-x0)*(y2-y0) - (y1-y0)*(x2-x0), reference rounding (no FMA)
    float area = __fsub_rn(__fmul_rn(__fsub_rn(x1, x0), __fsub_rn(y2, y0)),
                           __fmul_rn(__fsub_rn(y1, y0), __fsub_rn(x2, x0)));
    float s = (area > 0.0f) ? 1.0f : -1.0f;
    bool valid = fabsf(area) > 1e-12f;

    float4 bb, e0, e1, e2, wv;
    if (valid) {
        float inv = 1.0f / fabsf(area);
        // e0 = edge(v1, v2, p); e1 = edge(v2, v0, p); e2 = edge(v0, v1, p)
        e0 = make_float4(s * __fsub_rn(x2, x1), s * __fsub_rn(y2, y1), x1, y1);
        e1 = make_float4(s * __fsub_rn(x0, x2), s * __fsub_rn(y0, y2), x2, y2);
        e2 = make_float4(s * __fsub_rn(x1, x0), s * __fsub_rn(y1, y0), x0, y0);
        wv = make_float4(z0 * inv, z1 * inv, z2 * inv, 0.0f);
        bb = make_float4(fminf(x0, fminf(x1, x2)), fmaxf(x0, fmaxf(x1, x2)),
                         fminf(y0, fminf(y1, y2)), fmaxf(y0, fmaxf(y1, y2)));
    } else {
        // empty bbox guarantees cull; edge constants force e' < 0 as backup
        e0 = e1 = e2 = make_float4(0.0f, 1.0f, -4e9f, 0.0f);
        wv = make_float4(0.0f, 0.0f, 0.0f, 0.0f);
        bb = make_float4(3e38f, -3e38f, 3e38f, -3e38f);
    }
    float4* dst = g_face + (size_t)idx * 5;
    dst[0] = bb; dst[1] = e0; dst[2] = e1; dst[3] = e2; dst[4] = wv;
}

// Block tile: 32 output cols x 32 output rows. Warp = 32 cols x 4 rows
// (each thread owns a 4-pixel column). Grid z = batch * NSLICE + slice.
__global__ void __launch_bounds__(256) raster_kernel()
{
    __shared__ float4 sm[CHUNK * 5];

    int bz = blockIdx.z;
    int b = bz >> 2;          // NSLICE == 4
    int slice = bz & 3;
    int f0 = slice * CHUNK;
    int nf = min(NF - f0, CHUNK);

    const float4* src = g_face + (size_t)(b * NF + f0) * 5;
    for (int i = threadIdx.x; i < nf * 5; i += 256) sm[i] = src[i];
    __syncthreads();

    int lane = threadIdx.x & 31;
    int w = threadIdx.x >> 5;
    int col = blockIdx.x * 32 + lane;
    int row0 = blockIdx.y * 32 + w * 4;

    // render-space sample coords: x = 5*col + 2.5, y = 5*row + 2.5 (exact fp32)
    float px = 5.0f * (float)col + 2.5f;
    float py0 = 5.0f * (float)row0 + 2.5f;

    // warp tile bounds (uniform across warp) with 1px rounding margin
    float txmin = 5.0f * (float)(blockIdx.x * 32) + 2.5f - 1.0f;
    float txmax = txmin + 155.0f + 2.0f;
    float tymin = py0 - 1.0f;
    float tymax = tymin + 15.0f + 2.0f;

    float zb[4] = {BGD, BGD, BGD, BGD};

    for (int f = 0; f < nf; f++) {
        float4 bbx = sm[f * 5];
        // warp-uniform cull: bbox (expanded by margin) vs warp tile
        if (bbx.y < txmin || bbx.x > txmax || bbx.w < tymin || bbx.z > tymax)
            continue;

        float4 e0 = sm[f * 5 + 1];
        float4 e1 = sm[f * 5 + 2];
        float4 e2 = sm[f * 5 + 3];
        float4 wv = sm[f * 5 + 4];

        // per-column constants (x part of each edge fn), reference rounding
        float m20 = __fmul_rn(e0.y, __fsub_rn(px, e0.z));
        float m21 = __fmul_rn(e1.y, __fsub_rn(px, e1.z));
        float m22 = __fmul_rn(e2.y, __fsub_rn(px, e2.z));

#pragma unroll
        for (int k = 0; k < 4; k++) {
            float py = py0 + 5.0f * (float)k;   // exact
            float ea = __fsub_rn(__fmul_rn(e0.x, __fsub_rn(py, e0.w)), m20);
            float eb = __fsub_rn(__fmul_rn(e1.x, __fsub_rn(py, e1.w)), m21);
            float ec = __fsub_rn(__fmul_rn(e2.x, __fsub_rn(py, e2.w)), m22);
            if (fminf(ea, fminf(eb, ec)) >= 0.0f) {
                // continuous path: FMA + precomputed 1/|area| is safe
                float z = fmaf(ea, wv.x, fmaf(eb, wv.y, __fmul_rn(ec, wv.z)));
                zb[k] = fminf(zb[k], z);
            }
        }
    }

#pragma unroll
    for (int k = 0; k < 4; k++) {
        if (zb[k] < BGD) {
            unsigned int* dst = &g_zbuf[((size_t)b * OH + (row0 + k)) * OW + col];
            atomicMin(dst, __float_as_uint(zb[k]));
        }
    }
}

__global__ void __launch_bounds__(256) finalize_kernel(float* __restrict__ out)
{
    int idx = blockIdx.x * blockDim.x + threadIdx.x;
    if (idx < NB * OH * OW)
        out[idx] = fminf(__uint_as_float(g_zbuf[idx]), 100.0f);
}

extern "C" void kernel_launch(void* const* d_in, const int* in_sizes, int n_in,
                              void* d_out, int out_size)
{
    const float* verts = (const float*)d_in[0];
    const int* faces = (const int*)d_in[1];
    float* out = (float*)d_out;

    setup_kernel<<<(NB * OH * OW + 255) / 256, 256>>>(verts, faces);

    dim3 grid(OW / 32, OH / 32, NB * NSLICE);   // (4, 4, 16)
    raster_kernel<<<grid, 256>>>();

    finalize_kernel<<<(NB * OH * OW + 255) / 256, 256>>>(out);
}

// round 3
// speedup vs baseline: 1.3538x; 1.3538x over previous
#include <cuda_runtime.h>
#include <cstdint>

#define NV 778
#define NF 1538
#define NB 4
#define OW 128
#define OH 128
#define BGD 1e10f
#define NSLICE 16
#define CHUNK ((NF + NSLICE - 1) / NSLICE)   // 97

// Scratch (no allocation allowed): precomputed face data + uint z-buffer.
// Face record: 5 float4 per (batch, face):
//   [0] bbox  (xmin, xmax, ymin, ymax)
//   [1] edge0 (s*dx, s*dy, refx, refy)   e0' = s*dx*(py-refy) - s*dy*(px-refx)
//   [2] edge1
//   [3] edge2
//   [4] w     (z0/|area|, z1/|area|, z2/|area|, 0)
__device__ float4 g_face[NB * NF * 5];
__device__ unsigned int g_zbuf[NB * OH * OW];

__global__ void __launch_bounds__(256) setup_kernel(
    const float* __restrict__ verts, const int* __restrict__ faces)
{
    int idx = blockIdx.x * blockDim.x + threadIdx.x;

    // z-buffer init, vectorized (positive floats: uint order == float order)
    if (idx < (NB * OH * OW) / 4) {
        uint4 v;
        v.x = v.y = v.z = v.w = __float_as_uint(BGD);
        reinterpret_cast<uint4*>(g_zbuf)[idx] = v;
    }

    if (idx >= NB * NF) return;
    int b = idx / NF;
    int f = idx - b * NF;

    // faces land on device as int32 (JAX x64 disabled). Clamp defensively.
    int i0 = min(max(faces[f * 3 + 0], 0), NV - 1);
    int i1 = min(max(faces[f * 3 + 1], 0), NV - 1);
    int i2 = min(max(faces[f * 3 + 2], 0), NV - 1);
    const float* vb = verts + (size_t)b * NV * 3;
    float x0 = vb[i0 * 3 + 0], y0 = vb[i0 * 3 + 1], z0 = vb[i0 * 3 + 2];
    float x1 = vb[i1 * 3 + 0], y1 = vb[i1 * 3 + 1], z1 = vb[i1 * 3 + 2];
    float x2 = vb[i2 * 3 + 0], y2 = vb[i2 * 3 + 1], z2 = vb[i2 * 3 + 2];

    // area = (x1-x0)*(y2-y0) - (y1-y0)*(x2-x0), reference rounding (no FMA)
    float area = __fsub_rn(__fmul_rn(__fsub_rn(x1, x0), __fsub_rn(y2, y0)),
                           __fmul_rn(__fsub_rn(y1, y0), __fsub_rn(x2, x0)));
    float s = (area > 0.0f) ? 1.0f : -1.0f;
    bool valid = fabsf(area) > 1e-12f;

    float4 bb, e0, e1, e2, wv;
    if (valid) {
        float inv = 1.0f / fabsf(area);
        // e0 = edge(v1, v2, p); e1 = edge(v2, v0, p); e2 = edge(v0, v1, p)
        e0 = make_float4(s * __fsub_rn(x2, x1), s * __fsub_rn(y2, y1), x1, y1);
        e1 = make_float4(s * __fsub_rn(x0, x2), s * __fsub_rn(y0, y2), x2, y2);
        e2 = make_float4(s * __fsub_rn(x1, x0), s * __fsub_rn(y1, y0), x0, y0);
        wv = make_float4(z0 * inv, z1 * inv, z2 * inv, 0.0f);
        bb = make_float4(fminf(x0, fminf(x1, x2)), fmaxf(x0, fmaxf(x1, x2)),
                         fminf(y0, fminf(y1, y2)), fmaxf(y0, fmaxf(y1, y2)));
    } else {
        // empty bbox guarantees cull; edge constants force e' < 0 as backup
        e0 = e1 = e2 = make_float4(0.0f, 1.0f, -4e9f, 0.0f);
        wv = make_float4(0.0f, 0.0f, 0.0f, 0.0f);
        bb = make_float4(3e38f, -3e38f, 3e38f, -3e38f);
    }
    float4* dst = g_face + (size_t)idx * 5;
    dst[0] = bb; dst[1] = e0; dst[2] = e1; dst[3] = e2; dst[4] = wv;
}

// Block tile: 32 output cols x 32 output rows. Warp = 32 cols x 4 rows
// (each thread owns a 4-pixel column). Grid z = batch * NSLICE + slice.
__global__ void __launch_bounds__(256) raster_kernel()
{
    __shared__ float4 sm[CHUNK * 5];

    int bz = blockIdx.z;
    int b = bz >> 4;          // NSLICE == 16
    int slice = bz & 15;
    int f0 = slice * CHUNK;
    int nf = min(NF - f0, CHUNK);

    const float4* src = g_face + (size_t)(b * NF + f0) * 5;
    for (int i = threadIdx.x; i < nf * 5; i += 256) sm[i] = src[i];
    __syncthreads();

    int lane = threadIdx.x & 31;
    int w = threadIdx.x >> 5;
    int col = blockIdx.x * 32 + lane;
    int row0 = blockIdx.y * 32 + w * 4;

    // render-space sample coords: x = 5*col + 2.5, y = 5*row + 2.5 (exact fp32)
    float px = 5.0f * (float)col + 2.5f;
    float py0 = 5.0f * (float)row0 + 2.5f;

    // warp tile bounds (uniform across warp) with 1px rounding margin
    float txmin = 5.0f * (float)(blockIdx.x * 32) + 2.5f - 1.0f;
    float txmax = txmin + 155.0f + 2.0f;
    float tymin = py0 - 1.0f;
    float tymax = tymin + 15.0f + 2.0f;

    float zb[4] = {BGD, BGD, BGD, BGD};

    for (int f = 0; f < nf; f++) {
        float4 bbx = sm[f * 5];
        // warp-uniform cull: bbox (expanded by margin) vs warp tile
        if (bbx.y < txmin || bbx.x > txmax || bbx.w < tymin || bbx.z > tymax)
            continue;

        float4 e0 = sm[f * 5 + 1];
        float4 e1 = sm[f * 5 + 2];
        float4 e2 = sm[f * 5 + 3];
        float4 wv = sm[f * 5 + 4];

        // per-column constants (x part of each edge fn), reference rounding
        float m20 = __fmul_rn(e0.y, __fsub_rn(px, e0.z));
        float m21 = __fmul_rn(e1.y, __fsub_rn(px, e1.z));
        float m22 = __fmul_rn(e2.y, __fsub_rn(px, e2.z));

#pragma unroll
        for (int k = 0; k < 4; k++) {
            float py = py0 + 5.0f * (float)k;   // exact
            float ea = __fsub_rn(__fmul_rn(e0.x, __fsub_rn(py, e0.w)), m20);
            float eb = __fsub_rn(__fmul_rn(e1.x, __fsub_rn(py, e1.w)), m21);
            float ec = __fsub_rn(__fmul_rn(e2.x, __fsub_rn(py, e2.w)), m22);
            if (fminf(ea, fminf(eb, ec)) >= 0.0f) {
                // continuous path: FMA + precomputed 1/|area| is safe
                float z = fmaf(ea, wv.x, fmaf(eb, wv.y, __fmul_rn(ec, wv.z)));
                zb[k] = fminf(zb[k], z);
            }
        }
    }

#pragma unroll
    for (int k = 0; k < 4; k++) {
        if (zb[k] < BGD) {
            unsigned int* dst = &g_zbuf[((size_t)b * OH + (row0 + k)) * OW + col];
            atomicMin(dst, __float_as_uint(zb[k]));
        }
    }
}

__global__ void __launch_bounds__(256) finalize_kernel(float* __restrict__ out)
{
    int idx = blockIdx.x * blockDim.x + threadIdx.x;
    if (idx < (NB * OH * OW) / 4) {
        uint4 v = reinterpret_cast<const uint4*>(g_zbuf)[idx];
        float4 o;
        o.x = fminf(__uint_as_float(v.x), 100.0f);
        o.y = fminf(__uint_as_float(v.y), 100.0f);
        o.z = fminf(__uint_as_float(v.z), 100.0f);
        o.w = fminf(__uint_as_float(v.w), 100.0f);
        reinterpret_cast<float4*>(out)[idx] = o;
    }
}

extern "C" void kernel_launch(void* const* d_in, const int* in_sizes, int n_in,
                              void* d_out, int out_size)
{
    const float* verts = (const float*)d_in[0];
    const int* faces = (const int*)d_in[1];
    float* out = (float*)d_out;

    setup_kernel<<<64, 256>>>(verts, faces);

    dim3 grid(OW / 32, OH / 32, NB * NSLICE);   // (4, 4, 64)
    raster_kernel<<<grid, 256>>>();

    finalize_kernel<<<64, 256>>>(out);
}

// round 4
// speedup vs baseline: 1.5280x; 1.1287x over previous
#include <cuda_runtime.h>
#include <cstdint>

#define NV 778
#define NF 1538
#define NB 4
#define OW 128
#define OH 128
#define BGD 1e10f
#define NSLICE 32
#define CHUNK ((NF + NSLICE - 1) / NSLICE)   // 49

// Per-slice partial z-buffers (uint bits of positive floats; order-preserving).
// Layout: [slice][b][row][col]. 32*4*128*128*4B = 8 MB.
__device__ unsigned int g_part[NSLICE * NB * OH * OW];

// Fused kernel: per-CTA face setup (smem) + rasterize one 32x32 output tile
// for one (batch, face-slice). No atomics: each CTA owns its partial tile.
// Face record in smem: 5 float4:
//   [0] bbox (xmin, xmax, ymin, ymax)
//   [1..3] edges (s*dx, s*dy, refx, refy):  e' = s*dx*(py-refy) - s*dy*(px-refx)
//   [4] w (z0/|area|, z1/|area|, z2/|area|, 0)
__global__ void __launch_bounds__(256) raster_kernel(
    const float* __restrict__ verts, const int* __restrict__ faces)
{
    __shared__ float4 sm[CHUNK * 5];

    int bz = blockIdx.z;
    int b = bz >> 5;           // NSLICE == 32
    int slice = bz & 31;
    int f0 = slice * CHUNK;
    int nf = min(NF - f0, CHUNK);

    // ---- Phase 1: build this chunk's face records in smem ----
    int t = threadIdx.x;
    if (t < nf) {
        int f = f0 + t;
        // faces land on device as int32 (JAX x64 disabled). Clamp defensively.
        int i0 = min(max(faces[f * 3 + 0], 0), NV - 1);
        int i1 = min(max(faces[f * 3 + 1], 0), NV - 1);
        int i2 = min(max(faces[f * 3 + 2], 0), NV - 1);
        const float* vb = verts + (size_t)b * NV * 3;
        float x0 = vb[i0 * 3 + 0], y0 = vb[i0 * 3 + 1], z0 = vb[i0 * 3 + 2];
        float x1 = vb[i1 * 3 + 0], y1 = vb[i1 * 3 + 1], z1 = vb[i1 * 3 + 2];
        float x2 = vb[i2 * 3 + 0], y2 = vb[i2 * 3 + 1], z2 = vb[i2 * 3 + 2];

        // area with reference rounding (no FMA contraction)
        float area = __fsub_rn(__fmul_rn(__fsub_rn(x1, x0), __fsub_rn(y2, y0)),
                               __fmul_rn(__fsub_rn(y1, y0), __fsub_rn(x2, x0)));
        float s = (area > 0.0f) ? 1.0f : -1.0f;
        bool valid = fabsf(area) > 1e-12f;

        float4 bb, e0, e1, e2, wv;
        if (valid) {
            float inv = 1.0f / fabsf(area);
            e0 = make_float4(s * __fsub_rn(x2, x1), s * __fsub_rn(y2, y1), x1, y1);
            e1 = make_float4(s * __fsub_rn(x0, x2), s * __fsub_rn(y0, y2), x2, y2);
            e2 = make_float4(s * __fsub_rn(x1, x0), s * __fsub_rn(y1, y0), x0, y0);
            wv = make_float4(z0 * inv, z1 * inv, z2 * inv, 0.0f);
            bb = make_float4(fminf(x0, fminf(x1, x2)), fmaxf(x0, fmaxf(x1, x2)),
                             fminf(y0, fminf(y1, y2)), fmaxf(y0, fmaxf(y1, y2)));
        } else {
            e0 = e1 = e2 = make_float4(0.0f, 1.0f, -4e9f, 0.0f);
            wv = make_float4(0.0f, 0.0f, 0.0f, 0.0f);
            bb = make_float4(3e38f, -3e38f, 3e38f, -3e38f);   // cull always
        }
        float4* dst = sm + t * 5;
        dst[0] = bb; dst[1] = e0; dst[2] = e1; dst[3] = e2; dst[4] = wv;
    }
    __syncthreads();

    // ---- Phase 2: rasterize. Warp = 32 cols x 4 rows (thread owns a column
    //      of 4 pixels). Sample coords: x = 5*col+2.5, y = 5*row+2.5 (exact).
    int lane = threadIdx.x & 31;
    int w = threadIdx.x >> 5;
    int col = blockIdx.x * 32 + lane;
    int row0 = blockIdx.y * 32 + w * 4;

    float px = 5.0f * (float)col + 2.5f;
    float py0 = 5.0f * (float)row0 + 2.5f;

    // warp-uniform tile bounds with rounding margin
    float txmin = 5.0f * (float)(blockIdx.x * 32) + 2.5f - 1.0f;
    float txmax = txmin + 155.0f + 2.0f;
    float tymin = py0 - 1.0f;
    float tymax = tymin + 15.0f + 2.0f;

    float zb[4] = {BGD, BGD, BGD, BGD};

    for (int f = 0; f < nf; f++) {
        float4 bbx = sm[f * 5];
        if (bbx.y < txmin || bbx.x > txmax || bbx.w < tymin || bbx.z > tymax)
            continue;

        float4 e0 = sm[f * 5 + 1];
        float4 e1 = sm[f * 5 + 2];
        float4 e2 = sm[f * 5 + 3];
        float4 wv = sm[f * 5 + 4];

        // per-column constants (x part of each edge fn), reference rounding
        float m20 = __fmul_rn(e0.y, __fsub_rn(px, e0.z));
        float m21 = __fmul_rn(e1.y, __fsub_rn(px, e1.z));
        float m22 = __fmul_rn(e2.y, __fsub_rn(px, e2.z));

#pragma unroll
        for (int k = 0; k < 4; k++) {
            float py = py0 + 5.0f * (float)k;   // exact
            float ea = __fsub_rn(__fmul_rn(e0.x, __fsub_rn(py, e0.w)), m20);
            float eb = __fsub_rn(__fmul_rn(e1.x, __fsub_rn(py, e1.w)), m21);
            float ec = __fsub_rn(__fmul_rn(e2.x, __fsub_rn(py, e2.w)), m22);
            if (fminf(ea, fminf(eb, ec)) >= 0.0f) {
                // continuous path: FMA + precomputed 1/|area| is safe
                float z = fmaf(ea, wv.x, fmaf(eb, wv.y, __fmul_rn(ec, wv.z)));
                zb[k] = fminf(zb[k], z);
            }
        }
    }

    // ---- Phase 3: unconditional private-tile store (no atomics) ----
    unsigned int* base = g_part + ((size_t)(slice * NB + b) * OH) * OW;
#pragma unroll
    for (int k = 0; k < 4; k++)
        base[(size_t)(row0 + k) * OW + col] = __float_as_uint(zb[k]);
}

// Merge the 32 slice buffers, clamp, write output.
__global__ void __launch_bounds__(256) finalize_kernel(float* __restrict__ out)
{
    int idx = blockIdx.x * blockDim.x + threadIdx.x;   // uint4 granularity
    if (idx >= (NB * OH * OW) / 4) return;

    const uint4* p = reinterpret_cast<const uint4*>(g_part) + idx;
    const int stride = (NB * OH * OW) / 4;

    uint4 acc = p[0];
#pragma unroll
    for (int s = 1; s < NSLICE; s++) {
        uint4 v = p[(size_t)s * stride];
        acc.x = min(acc.x, v.x);
        acc.y = min(acc.y, v.y);
        acc.z = min(acc.z, v.z);
        acc.w = min(acc.w, v.w);
    }
    float4 o;
    o.x = fminf(__uint_as_float(acc.x), 100.0f);
    o.y = fminf(__uint_as_float(acc.y), 100.0f);
    o.z = fminf(__uint_as_float(acc.z), 100.0f);
    o.w = fminf(__uint_as_float(acc.w), 100.0f);
    reinterpret_cast<float4*>(out)[idx] = o;
}

extern "C" void kernel_launch(void* const* d_in, const int* in_sizes, int n_in,
                              void* d_out, int out_size)
{
    const float* verts = (const float*)d_in[0];
    const int* faces = (const int*)d_in[1];
    float* out = (float*)d_out;

    dim3 grid(OW / 32, OH / 32, NB * NSLICE);   // (4, 4, 128) = 2048 CTAs
    raster_kernel<<<grid, 256>>>(verts, faces);

    finalize_kernel<<<64, 256>>>(out);
}

// round 5
// speedup vs baseline: 1.8723x; 1.2254x over previous
#include <cuda_runtime.h>
#include <cstdint>

#define NV 778
#define NF 1538
#define NB 4
#define OW 128
#define OH 128
#define BGD 1e10f
#define NSLICE 32
#define CHUNK ((NF + NSLICE - 1) / NSLICE)        // 49
#define NROUND ((CHUNK + 31) / 32)                // 2

// Per-slice partial z-buffers (uint bits of positive floats; order-preserving).
// Layout: [slice][b][row][col]. 32*4*128*128*4B = 8 MB.
__device__ unsigned int g_part[NSLICE * NB * OH * OW];

// Fused kernel: per-CTA face setup (smem, SoA) + ballot-compacted raster of
// one 32x32 output tile for one (batch, face-slice). No atomics.
__global__ void __launch_bounds__(256) raster_kernel(
    const float* __restrict__ verts, const int* __restrict__ faces)
{
    // SoA: bboxes separate so the scan phase does one coalesced LDS.128/lane.
    __shared__ float4 sbb[CHUNK];          // (xmin, xmax, ymin, ymax)
    __shared__ float4 sed[CHUNK * 4];      // e0,e1,e2,w per face
    //   e: (s*dx, s*dy, refx, refy)  ->  e' = s*dx*(py-refy) - s*dy*(px-refx)
    //   w: (z0/|area|, z1/|area|, z2/|area|, 0)

    int bz = blockIdx.z;
    int b = bz >> 5;           // NSLICE == 32
    int slice = bz & 31;
    int f0 = slice * CHUNK;
    int nf = min(NF - f0, CHUNK);

    // ---- Phase 1: build this chunk's face records in smem ----
    int t = threadIdx.x;
    if (t < nf) {
        int f = f0 + t;
        // faces land on device as int32 (JAX x64 disabled). Clamp defensively.
        int i0 = min(max(faces[f * 3 + 0], 0), NV - 1);
        int i1 = min(max(faces[f * 3 + 1], 0), NV - 1);
        int i2 = min(max(faces[f * 3 + 2], 0), NV - 1);
        const float* vb = verts + (size_t)b * NV * 3;
        float x0 = vb[i0 * 3 + 0], y0 = vb[i0 * 3 + 1], z0 = vb[i0 * 3 + 2];
        float x1 = vb[i1 * 3 + 0], y1 = vb[i1 * 3 + 1], z1 = vb[i1 * 3 + 2];
        float x2 = vb[i2 * 3 + 0], y2 = vb[i2 * 3 + 1], z2 = vb[i2 * 3 + 2];

        // area with reference rounding (no FMA contraction)
        float area = __fsub_rn(__fmul_rn(__fsub_rn(x1, x0), __fsub_rn(y2, y0)),
                               __fmul_rn(__fsub_rn(y1, y0), __fsub_rn(x2, x0)));
        float s = (area > 0.0f) ? 1.0f : -1.0f;
        bool valid = fabsf(area) > 1e-12f;

        float4 bb, e0, e1, e2, wv;
        if (valid) {
            float inv = 1.0f / fabsf(area);
            e0 = make_float4(s * __fsub_rn(x2, x1), s * __fsub_rn(y2, y1), x1, y1);
            e1 = make_float4(s * __fsub_rn(x0, x2), s * __fsub_rn(y0, y2), x2, y2);
            e2 = make_float4(s * __fsub_rn(x1, x0), s * __fsub_rn(y1, y0), x0, y0);
            wv = make_float4(z0 * inv, z1 * inv, z2 * inv, 0.0f);
            bb = make_float4(fminf(x0, fminf(x1, x2)), fmaxf(x0, fmaxf(x1, x2)),
                             fminf(y0, fminf(y1, y2)), fmaxf(y0, fmaxf(y1, y2)));
        } else {
            e0 = e1 = e2 = make_float4(0.0f, 1.0f, -4e9f, 0.0f);
            wv = make_float4(0.0f, 0.0f, 0.0f, 0.0f);
            bb = make_float4(3e38f, -3e38f, 3e38f, -3e38f);   // cull always
        }
        sbb[t] = bb;
        sed[t * 4 + 0] = e0;
        sed[t * 4 + 1] = e1;
        sed[t * 4 + 2] = e2;
        sed[t * 4 + 3] = wv;
    }
    __syncthreads();

    // ---- Phase 2: rasterize. Warp = 32 cols x 4 rows (thread owns a column
    //      of 4 pixels). Sample coords: x = 5*col+2.5, y = 5*row+2.5 (exact).
    int lane = threadIdx.x & 31;
    int w = threadIdx.x >> 5;
    int col = blockIdx.x * 32 + lane;
    int row0 = blockIdx.y * 32 + w * 4;

    float px = 5.0f * (float)col + 2.5f;
    float py0 = 5.0f * (float)row0 + 2.5f;

    // warp-uniform tile bounds with rounding margin
    float txmin = 5.0f * (float)(blockIdx.x * 32) + 2.5f - 1.0f;
    float txmax = txmin + 155.0f + 2.0f;
    float tymin = py0 - 1.0f;
    float tymax = tymin + 15.0f + 2.0f;

    // Scan: lane L tests face (r*32 + L); ballot builds the pass mask.
    unsigned int mask[NROUND];
#pragma unroll
    for (int r = 0; r < NROUND; r++) {
        int f = r * 32 + lane;
        bool pass = false;
        if (f < nf) {
            float4 bb = sbb[f];
            pass = !(bb.y < txmin || bb.x > txmax || bb.w < tymin || bb.z > tymax);
        }
        mask[r] = __ballot_sync(0xFFFFFFFFu, pass);
    }

    float zb[4] = {BGD, BGD, BGD, BGD};

#pragma unroll
    for (int r = 0; r < NROUND; r++) {
        unsigned int m = mask[r];
        while (m) {
            int i = __ffs(m) - 1;
            m &= m - 1;
            int f = r * 32 + i;

            float4 e0 = sed[f * 4 + 0];
            float4 e1 = sed[f * 4 + 1];
            float4 e2 = sed[f * 4 + 2];
            float4 wv = sed[f * 4 + 3];

            // per-column constants (x part of each edge fn), reference rounding
            float m20 = __fmul_rn(e0.y, __fsub_rn(px, e0.z));
            float m21 = __fmul_rn(e1.y, __fsub_rn(px, e1.z));
            float m22 = __fmul_rn(e2.y, __fsub_rn(px, e2.z));

#pragma unroll
            for (int k = 0; k < 4; k++) {
                float py = py0 + 5.0f * (float)k;   // exact
                float ea = __fsub_rn(__fmul_rn(e0.x, __fsub_rn(py, e0.w)), m20);
                float eb = __fsub_rn(__fmul_rn(e1.x, __fsub_rn(py, e1.w)), m21);
                float ec = __fsub_rn(__fmul_rn(e2.x, __fsub_rn(py, e2.w)), m22);
                if (fminf(ea, fminf(eb, ec)) >= 0.0f) {
                    // continuous path: FMA + precomputed 1/|area| is safe
                    float z = fmaf(ea, wv.x, fmaf(eb, wv.y, __fmul_rn(ec, wv.z)));
                    zb[k] = fminf(zb[k], z);
                }
            }
        }
    }

    // ---- Phase 3: unconditional private-tile store (no atomics) ----
    unsigned int* base = g_part + ((size_t)(slice * NB + b) * OH) * OW;
#pragma unroll
    for (int k = 0; k < 4; k++)
        base[(size_t)(row0 + k) * OW + col] = __float_as_uint(zb[k]);
}

// Merge the 32 slice buffers, clamp, write output. One uint per thread:
// 65536 threads / 256 CTAs -> every SM busy, 32 independent loads per thread.
__global__ void __launch_bounds__(256) finalize_kernel(float* __restrict__ out)
{
    int idx = blockIdx.x * blockDim.x + threadIdx.x;
    if (idx >= NB * OH * OW) return;

    const unsigned int* p = g_part + idx;
    const int stride = NB * OH * OW;

    unsigned int acc = p[0];
#pragma unroll
    for (int s = 1; s < NSLICE; s++)
        acc = min(acc, p[(size_t)s * stride]);

    out[idx] = fminf(__uint_as_float(acc), 100.0f);
}

extern "C" void kernel_launch(void* const* d_in, const int* in_sizes, int n_in,
                              void* d_out, int out_size)
{
    const float* verts = (const float*)d_in[0];
    const int* faces = (const int*)d_in[1];
    float* out = (float*)d_out;

    dim3 grid(OW / 32, OH / 32, NB * NSLICE);   // (4, 4, 128) = 2048 CTAs
    raster_kernel<<<grid, 256>>>(verts, faces);

    finalize_kernel<<<(NB * OH * OW + 255) / 256, 256>>>(out);
}